// round 6
// baseline (speedup 1.0000x reference)
#include <cuda_runtime.h>
#include <cstdint>

// Problem constants (from reference: B=8192, T=512, H=W=64)
#define WIDTH   64
#define HW      4096        // H*W cells per map
#define NB      16          // batches per block
#define NTHREADS 128
#define MAP_WORDS 256       // HW/16 packed uint32 words per batch (2 bits/cell)

// dynamic smem layout:
//   [0, NB*MAP_WORDS*4)              : packed maps (16 KB)
//   [NB*MAP_WORDS*4, + NB*T bytes)   : actions as bytes (8 KB for T=512)

__global__ __launch_bounds__(NTHREADS, 1)
void rollout_kernel(const float* __restrict__ s0,
                    const int*   __restrict__ a,
                    const float* __restrict__ world,
                    float* __restrict__ out_s,   // [B, T+1, 2]
                    float* __restrict__ out_r,   // [B, T+1]
                    int B, int T)
{
    extern __shared__ unsigned char smem[];
    uint32_t* maps = reinterpret_cast<uint32_t*>(smem);                     // NB*MAP_WORDS
    uint8_t*  acts = reinterpret_cast<uint8_t*>(smem) + NB * MAP_WORDS * 4; // NB*T

    const int b0  = blockIdx.x * NB;
    const int tid = threadIdx.x;

    // ---------- Phase 1a: pack maps (wall bit0, goal bit1; 2 bits/cell) ----------
    for (int w = tid; w < NB * MAP_WORDS; w += NTHREADS) {
        const int bi   = w >> 8;          // batch within block (w / MAP_WORDS)
        const int word = w & (MAP_WORDS - 1);
        const int b    = b0 + bi;
        uint32_t code = 0;
        if (b < B) {
            const float* wallp = world + (size_t)b * 2 * HW + word * 16;
            const float* goalp = wallp + HW;
            #pragma unroll
            for (int j = 0; j < 4; j++) {
                float4 wv = *reinterpret_cast<const float4*>(wallp + j * 4);
                float4 gv = *reinterpret_cast<const float4*>(goalp + j * 4);
                uint32_t c0 = (wv.x == 1.0f ? 1u : 0u) | (gv.x == 10.0f ? 2u : 0u);
                uint32_t c1 = (wv.y == 1.0f ? 1u : 0u) | (gv.y == 10.0f ? 2u : 0u);
                uint32_t c2 = (wv.z == 1.0f ? 1u : 0u) | (gv.z == 10.0f ? 2u : 0u);
                uint32_t c3 = (wv.w == 1.0f ? 1u : 0u) | (gv.w == 10.0f ? 2u : 0u);
                code |= (c0 | (c1 << 2) | (c2 << 4) | (c3 << 6)) << (8 * j);
            }
        }
        maps[w] = code;
    }

    // ---------- Phase 1b: stage actions as bytes ----------
    {
        const int total4 = (NB * T) / 4;                 // int4 chunks
        const int4* ap = reinterpret_cast<const int4*>(a + (size_t)b0 * T);
        uint32_t* actw = reinterpret_cast<uint32_t*>(acts);
        const int maxb = B - b0;
        for (int i = tid; i < total4; i += NTHREADS) {
            int bi = (i * 4) / T;
            uint32_t packed = 0;
            if (bi < maxb) {
                int4 v = ap[i];
                packed = (uint32_t)(v.x & 0xff)
                       | ((uint32_t)(v.y & 0xff) << 8)
                       | ((uint32_t)(v.z & 0xff) << 16)
                       | ((uint32_t)(v.w & 0xff) << 24);
            }
            actw[i] = packed;
        }
    }

    __syncthreads();

    // ---------- Phase 2: sequential rollouts, one thread per batch ----------
    if (tid < NB) {
        const int b = b0 + tid;
        if (b < B) {
            int si = (int)s0[2 * b + 0];
            int sj = (int)s0[2 * b + 1];

            float2* sp = reinterpret_cast<float2*>(out_s + (size_t)b * (T + 1) * 2);
            float*  rp = out_r + (size_t)b * (T + 1);

            sp[0] = make_float2((float)si, (float)sj);
            rp[0] = 0.0f;

            const uint32_t* mymap = maps + tid * MAP_WORDS;
            const uint8_t*  myact = acts + (size_t)tid * T;

            // Prefetch the first action; action stream is independent of the
            // state chain, so keep one iteration of lookahead in flight.
            int at = myact[0];
            for (int t = 0; t < T; t++) {
                int at_next = (t + 1 < T) ? myact[t + 1] : 0;
                int dr = (at == 1 ? -1 : 0) + (at == 2 ? 1 : 0);
                int dc = (at == 3 ? -1 : 0) + (at == 4 ? 1 : 0);
                int ni = si + dr;
                int nj = sj + dc;
                int idx = ni * WIDTH + nj;
                // JAX take_along_axis semantics:
                //   idx in [-HW, -1]  -> wraps: reads flat cell idx + HW
                //   idx in [0, HW-1]  -> direct read
                //   otherwise         -> fill (NaN): neither goal nor wall,
                //                        r = -0.01, move accepted.
                int  eidx  = (idx < 0) ? idx + HW : idx;
                bool valid = (eidx >= 0) && (eidx < HW);
                uint32_t code = 0;
                if (valid) code = (mymap[eidx >> 4] >> ((eidx & 15) * 2)) & 3u;
                bool goal = (code & 2u) != 0u;
                bool wall = (!goal) && ((code & 1u) != 0u);
                float r = goal ? 1.0f : (wall ? -1.0f : -0.01f);
                if (!wall) { si = ni; sj = nj; }   // revert only on wall hit
                sp[t + 1] = make_float2((float)si, (float)sj);
                rp[t + 1] = r;
                at = at_next;
            }
        }
    }
}

extern "C" void kernel_launch(void* const* d_in, const int* in_sizes, int n_in,
                              void* d_out, int out_size)
{
    const float* s0    = (const float*)d_in[0];   // [B, 2]
    const int*   a     = (const int*)  d_in[1];   // [B, T]
    const float* world = (const float*)d_in[2];   // [B, 2, 64, 64]

    const int B = in_sizes[0] / 2;
    const int T = in_sizes[1] / B;

    float* out_s = (float*)d_out;                       // [B, T+1, 2]
    float* out_r = out_s + (size_t)B * (T + 1) * 2;     // [B, T+1]

    const int smem_bytes = NB * MAP_WORDS * 4 + NB * T; // 16KB + 8KB = 24KB
    cudaFuncSetAttribute(rollout_kernel,
                         cudaFuncAttributeMaxDynamicSharedMemorySize, smem_bytes);

    const int grid = (B + NB - 1) / NB;                 // 512
    rollout_kernel<<<grid, NTHREADS, smem_bytes>>>(s0, a, world, out_s, out_r, B, T);
}

// round 7
// speedup vs baseline: 1.0298x; 1.0298x over previous
#include <cuda_runtime.h>
#include <cstdint>

// Problem constants (from reference: B=8192, T=512, H=W=64)
#define WIDTH   64
#define HW      4096        // H*W cells per map
#define NB      16          // batches per block
#define NTHREADS 128
#define MAP_WORDS 256       // HW/16 packed uint32 words per batch (2 bits/cell)
#define CHUNK   64          // rollout steps staged per flush
#define SPAD    65          // float2 row stride for stage_s (pad -> conflict-free)
#define RPAD    65          // float  row stride for stage_r

// dynamic smem layout:
//   maps    : NB*MAP_WORDS uint32            (16 KB)
//   acts    : NB*T bytes                     ( 8 KB)
//   stage_s : NB*SPAD float2                 (8320 B)
//   stage_r : NB*RPAD float                  (4160 B)

__global__ __launch_bounds__(NTHREADS, 1)
void rollout_kernel(const float* __restrict__ s0,
                    const int*   __restrict__ a,
                    const float* __restrict__ world,
                    float* __restrict__ out_s,   // [B, T+1, 2]
                    float* __restrict__ out_r,   // [B, T+1]
                    int B, int T)
{
    extern __shared__ unsigned char smem[];
    uint32_t* maps    = reinterpret_cast<uint32_t*>(smem);                       // NB*MAP_WORDS
    uint8_t*  acts    = reinterpret_cast<uint8_t*>(smem) + NB * MAP_WORDS * 4;   // NB*T
    float2*   stage_s = reinterpret_cast<float2*>(acts + NB * 512);              // NB*SPAD
    float*    stage_r = reinterpret_cast<float*>(stage_s + NB * SPAD);           // NB*RPAD

    const int b0  = blockIdx.x * NB;
    const int tid = threadIdx.x;

    // ---------- Phase 1a: pack maps (wall bit0, goal bit1; 2 bits/cell) ----------
    for (int w = tid; w < NB * MAP_WORDS; w += NTHREADS) {
        const int bi   = w >> 8;          // w / MAP_WORDS
        const int word = w & (MAP_WORDS - 1);
        const int b    = b0 + bi;
        uint32_t code = 0;
        if (b < B) {
            const float* wallp = world + (size_t)b * 2 * HW + word * 16;
            const float* goalp = wallp + HW;
            #pragma unroll
            for (int j = 0; j < 4; j++) {
                float4 wv = *reinterpret_cast<const float4*>(wallp + j * 4);
                float4 gv = *reinterpret_cast<const float4*>(goalp + j * 4);
                uint32_t c0 = (wv.x == 1.0f ? 1u : 0u) | (gv.x == 10.0f ? 2u : 0u);
                uint32_t c1 = (wv.y == 1.0f ? 1u : 0u) | (gv.y == 10.0f ? 2u : 0u);
                uint32_t c2 = (wv.z == 1.0f ? 1u : 0u) | (gv.z == 10.0f ? 2u : 0u);
                uint32_t c3 = (wv.w == 1.0f ? 1u : 0u) | (gv.w == 10.0f ? 2u : 0u);
                code |= (c0 | (c1 << 2) | (c2 << 4) | (c3 << 6)) << (8 * j);
            }
        }
        maps[w] = code;
    }

    // ---------- Phase 1b: stage actions as bytes ----------
    {
        const int total4 = (NB * T) / 4;
        const int4* ap = reinterpret_cast<const int4*>(a + (size_t)b0 * T);
        uint32_t* actw = reinterpret_cast<uint32_t*>(acts);
        const int maxb = B - b0;
        for (int i = tid; i < total4; i += NTHREADS) {
            int bi = (i * 4) / T;
            uint32_t packed = 0;
            if (bi < maxb) {
                int4 v = ap[i];
                packed = (uint32_t)(v.x & 0xff)
                       | ((uint32_t)(v.y & 0xff) << 8)
                       | ((uint32_t)(v.z & 0xff) << 16)
                       | ((uint32_t)(v.w & 0xff) << 24);
            }
            actw[i] = packed;
        }
    }

    __syncthreads();

    // ---------- Phase 2: chunked rollout + coalesced flush ----------
    // Rollout state lives in registers of threads 0..NB-1 across chunks.
    int si = 0, sj = 0;
    const bool roller = (tid < NB) && (b0 + tid < B);
    const uint32_t* mymap = maps + tid * MAP_WORDS;
    const uint8_t*  myact = acts + (size_t)tid * T;

    if (roller) {
        const int b = b0 + tid;
        si = (int)s0[2 * b + 0];
        sj = (int)s0[2 * b + 1];
        // t=0 outputs written directly (scattered, but only once per batch)
        reinterpret_cast<float2*>(out_s)[(size_t)b * (T + 1)] =
            make_float2((float)si, (float)sj);
        out_r[(size_t)b * (T + 1)] = 0.0f;
    }

    for (int c0 = 0; c0 < T; c0 += CHUNK) {
        // -- rollout CHUNK steps into smem stage (threads 0..NB-1) --
        if (roller) {
            float2* ss = stage_s + tid * SPAD;
            float*  sr = stage_r + tid * RPAD;
            int at = myact[c0];
            #pragma unroll 4
            for (int k = 0; k < CHUNK; k++) {
                int t = c0 + k;
                int at_next = (t + 1 < T) ? myact[t + 1] : 0;
                int dr = (at == 1 ? -1 : 0) + (at == 2 ? 1 : 0);
                int dc = (at == 3 ? -1 : 0) + (at == 4 ? 1 : 0);
                int ni = si + dr;
                int nj = sj + dc;
                int idx = ni * WIDTH + nj;
                // JAX take_along_axis: negative wraps (+HW); beyond [-HW,HW) -> NaN fill
                //  -> neither goal nor wall -> r=-0.01, move accepted.
                int  eidx  = (idx < 0) ? idx + HW : idx;
                bool valid = (eidx >= 0) && (eidx < HW);
                uint32_t code = 0;
                if (valid) code = (mymap[eidx >> 4] >> ((eidx & 15) * 2)) & 3u;
                bool goal = (code & 2u) != 0u;
                bool wall = (!goal) && ((code & 1u) != 0u);
                float r = goal ? 1.0f : (wall ? -1.0f : -0.01f);
                if (!wall) { si = ni; sj = nj; }
                ss[k] = make_float2((float)si, (float)sj);
                sr[k] = r;
                at = at_next;
            }
        }
        __syncthreads();

        // -- flush stage to global, fully coalesced (all 128 threads) --
        // NB*CHUNK = 1024 elements each for s (float2) and r (float).
        {
            const int steps = min(CHUNK, T - c0);
            #pragma unroll
            for (int n = 0; n < (NB * CHUNK) / NTHREADS; n++) {
                int g  = tid + n * NTHREADS;
                int bi = g >> 6;          // g / CHUNK
                int k  = g & (CHUNK - 1);
                int b  = b0 + bi;
                if (b < B && k < steps) {
                    reinterpret_cast<float2*>(out_s)[(size_t)b * (T + 1) + c0 + 1 + k] =
                        stage_s[bi * SPAD + k];
                    out_r[(size_t)b * (T + 1) + c0 + 1 + k] = stage_r[bi * RPAD + k];
                }
            }
        }
        __syncthreads();
    }
}

extern "C" void kernel_launch(void* const* d_in, const int* in_sizes, int n_in,
                              void* d_out, int out_size)
{
    const float* s0    = (const float*)d_in[0];   // [B, 2]
    const int*   a     = (const int*)  d_in[1];   // [B, T]
    const float* world = (const float*)d_in[2];   // [B, 2, 64, 64]

    const int B = in_sizes[0] / 2;
    const int T = in_sizes[1] / B;

    float* out_s = (float*)d_out;                       // [B, T+1, 2]
    float* out_r = out_s + (size_t)B * (T + 1) * 2;     // [B, T+1]

    const int smem_bytes = NB * MAP_WORDS * 4 + NB * T
                         + NB * SPAD * 8 + NB * RPAD * 4;   // ~37 KB
    cudaFuncSetAttribute(rollout_kernel,
                         cudaFuncAttributeMaxDynamicSharedMemorySize, smem_bytes);

    const int grid = (B + NB - 1) / NB;                 // 512
    rollout_kernel<<<grid, NTHREADS, smem_bytes>>>(s0, a, world, out_s, out_r, B, T);
}